// round 15
// baseline (speedup 1.0000x reference)
#include <cuda_runtime.h>
#include <cuda_fp16.h>
#include <cstdint>

#define NN 50000
#define NE 800000
#define AF 133
#define BF 14
#define H  128
#define SA_STRIDE 136
#define SD_STRIDE 132
#define BMAT (128 * SA_STRIDE)          // elems per 128x128 16-bit smem matrix
#define ETILE 128
#define TILES_PER_CTA 5
#define EGRID (NE / ETILE / TILES_PER_CTA)   // 1250

#define NGS  152
#define NGMAT (128 * NGS)
#define NROWS_PAD 50048
#define NGRID 391

// ---------------- scratch ----------------
__device__ __half g_h [(size_t)NE * H];            // edge hidden (fp16)
__device__ __half g_y1[(size_t)NE * H];            // Y (fp16)
__device__ __half g_y2[(size_t)NE * H];
__device__ float g_P [(size_t)NN * H];
__device__ float g_S1[(size_t)NN * H];
__device__ float g_S2[(size_t)NN * H];
__device__ float g_S3[(size_t)NN * H];
__device__ float g_WbT[BF * H];
__device__ __half g_B [H * H];                     // Wh (fp16)  [n][k]
__device__ __half g_W1[128 * 144];                 // Wa padded (fp16) [n][k]
__device__ __half g_W2[128 * 288];                 // Wo padded (fp16) [n][k]
__device__ __half g_A1[(size_t)NROWS_PAD * 144];   // atom panel (fp16)
__device__ __half g_A2[(size_t)NROWS_PAD * 288];   // [atom|S3] panel (fp16)
__device__ int   g_idx64;

// ---------------- helpers ----------------
__device__ __forceinline__ int ld_idx(const void* p, long i) {
    if (g_idx64) return (int)__ldg((const long long*)p + i);
    return __ldg((const int*)p + i);
}
__device__ __forceinline__ void red4(float* p, float4 v) {
    asm volatile("red.global.add.v4.f32 [%0], {%1,%2,%3,%4};"
                 :: "l"(p), "f"(v.x), "f"(v.y), "f"(v.z), "f"(v.w) : "memory");
}
__device__ __forceinline__ uint32_t smem_u32(const void* p) {
    uint32_t a;
    asm("{ .reg .u64 t; cvta.to.shared.u64 t, %1; cvt.u32.u64 %0, t; }" : "=r"(a) : "l"(p));
    return a;
}
__device__ __forceinline__ void cp_async16(uint32_t sdst, const void* gsrc) {
    asm volatile("cp.async.cg.shared.global [%0], [%1], 16;" :: "r"(sdst), "l"(gsrc) : "memory");
}
__device__ __forceinline__ void cp_commit() {
    asm volatile("cp.async.commit_group;" ::: "memory");
}
template<int N> __device__ __forceinline__ void cp_wait() {
    asm volatile("cp.async.wait_group %0;" :: "n"(N) : "memory");
}
__device__ __forceinline__ void ldsm_x4(uint32_t (&r)[4], uint32_t addr) {
    asm volatile("ldmatrix.sync.aligned.m8n8.x4.shared.b16 {%0,%1,%2,%3}, [%4];"
                 : "=r"(r[0]), "=r"(r[1]), "=r"(r[2]), "=r"(r[3]) : "r"(addr));
}
__device__ __forceinline__ void ldsm_x2(uint32_t (&r)[2], uint32_t addr) {
    asm volatile("ldmatrix.sync.aligned.m8n8.x2.shared.b16 {%0,%1}, [%2];"
                 : "=r"(r[0]), "=r"(r[1]) : "r"(addr));
}
__device__ __forceinline__ void mma_f16(float (&d)[4], const uint32_t (&a)[4], const uint32_t (&b)[2]) {
    asm volatile("mma.sync.aligned.m16n8k16.row.col.f32.f16.f16.f32 "
                 "{%0,%1,%2,%3}, {%4,%5,%6,%7}, {%8,%9}, {%0,%1,%2,%3};"
                 : "+f"(d[0]), "+f"(d[1]), "+f"(d[2]), "+f"(d[3])
                 : "r"(a[0]), "r"(a[1]), "r"(a[2]), "r"(a[3]), "r"(b[0]), "r"(b[1]));
}
__device__ __forceinline__ float4 ld_y4(const __half* p) {
    uint2 raw = __ldg((const uint2*)p);
    __half2 h01 = *(__half2*)&raw.x;
    __half2 h23 = *(__half2*)&raw.y;
    float2 f01 = __half22float2(h01);
    float2 f23 = __half22float2(h23);
    return make_float4(f01.x, f01.y, f23.x, f23.y);
}

// ======= prep_all: zero S bufs | weight prep | atom panel | idx detect ======
#define ZB 18750
#define WB 144
#define CB 28152
__global__ __launch_bounds__(256) void prep_all(
    const float* __restrict__ Wi, const float* __restrict__ Wh,
    const float* __restrict__ Wo, const float* __restrict__ atom,
    const unsigned int* __restrict__ srcw,
    float4* __restrict__ S1, float4* __restrict__ S2, float4* __restrict__ S3)
{
    int b = blockIdx.x;
    if (b < ZB) {
        const long n = (long)NN * H / 4;
        long i = (long)b * 256 + threadIdx.x;
        float4 z = make_float4(0.f, 0.f, 0.f, 0.f);
        if (i < n) S1[i] = z;
        else if (i < 2 * n) S2[i - n] = z;
        else S3[i - 2 * n] = z;
        return;
    }
    b -= ZB;
    if (b < WB) {
        int i = b * 256 + threadIdx.x;
        if (i >= 128 * 288) return;
        if (i < BF * H) {
            int j = i & 127, k = i >> 7;
            g_WbT[i] = Wi[j * (AF + BF) + AF + k];
        }
        if (i < H * H)
            g_B[i] = __float2half_rn(Wh[i]);
        if (i < 128 * 144) {
            int n = i / 144, k = i % 144;
            g_W1[i] = __float2half_rn((k < AF) ? Wi[n * (AF + BF) + k] : 0.f);
        }
        {
            int n = i / 288, k = i % 288;
            g_W2[i] = __float2half_rn((k < AF + H) ? Wo[n * (AF + H) + k] : 0.f);
        }
        return;
    }
    b -= WB;
    if (b < CB) {
        long i = (long)b * 256 + threadIdx.x;
        int r = (int)(i / 144), c = (int)(i % 144);
        float v = (r < NN && c < AF) ? __ldg(atom + (size_t)r * AF + c) : 0.f;
        g_A1[i] = __float2half_rn(v);
        return;
    }
    __shared__ unsigned int s;
    if (threadIdx.x == 0) s = 0;
    __syncthreads();
    unsigned int v = srcw[threadIdx.x * 2 + 1] | srcw[2048 + threadIdx.x * 2 + 1];
    atomicOr(&s, v);
    __syncthreads();
    if (threadIdx.x == 0) g_idx64 = (s == 0u) ? 1 : 0;
}

// ---------------- cvt2: [atom|S3] panel (fp16) ----------------
__global__ void cvt2(const float* __restrict__ atom, const float* __restrict__ S3) {
    long i = (long)blockIdx.x * blockDim.x + threadIdx.x;
    if (i >= (long)NROWS_PAD * 288) return;
    int r = (int)(i / 288), c = (int)(i % 288);
    float v = 0.f;
    if (r < NN) {
        if (c < AF) v = __ldg(atom + (size_t)r * AF + c);
        else if (c < AF + H) v = __ldg(S3 + (size_t)r * H + (c - AF));
    }
    g_A2[i] = __float2half_rn(v);
}

// ---------------- node GEMM via mma.sync (single fp16, 1 pass) ---------------
template<int KPAD, bool RELU>
__global__ __launch_bounds__(512, 1) void ngemm(
    const __half* __restrict__ Ag, const __half* __restrict__ Wg,
    float* __restrict__ out)
{
    extern __shared__ __align__(16) char dyn[];
    __half* sB = (__half*)dyn;
    __half* sA = sB + NGMAT;
    float*  sD = (float*)(sA + NGMAT);   // dedicated staging

    int tid = threadIdx.x, lane = tid & 31, wid = tid >> 5;
    int m0 = blockIdx.x * 128;
    int wm = (wid >> 2) * 32, wn = (wid & 3) * 32;

    float acc[2][4][4];
    #pragma unroll
    for (int mt = 0; mt < 2; mt++)
        #pragma unroll
        for (int nt = 0; nt < 4; nt++)
            #pragma unroll
            for (int i = 0; i < 4; i++) acc[mt][nt][i] = 0.f;

    const int NCH = KPAD / 144;
    #pragma unroll
    for (int ch = 0; ch < NCH; ch++) {
        if (ch) __syncthreads();
        for (int i = tid; i < 128 * 18; i += 512) {
            int r = i / 18, c = i % 18;
            int go = r * KPAD + ch * 144 + c * 8;
            *(uint4*)(sB + r * NGS + c * 8) = *(const uint4*)(Wg + go);
        }
        for (int i = tid; i < 128 * 18; i += 512) {
            int r = i / 18, c = i % 18;
            size_t go = (size_t)(m0 + r) * KPAD + ch * 144 + c * 8;
            *(uint4*)(sA + r * NGS + c * 8) = *(const uint4*)(Ag + go);
        }
        __syncthreads();

        uint32_t aAddr0 = smem_u32(sA) + ((uint32_t)(wm + (lane & 15)) * NGS + (lane >> 4) * 8) * 2;
        uint32_t aAddr1 = aAddr0 + 16 * NGS * 2;
        uint32_t bAddr  = smem_u32(sB) + ((uint32_t)(wn + (lane & 7)) * NGS + ((lane >> 3) & 1) * 8) * 2;
        #pragma unroll
        for (int ks = 0; ks < 9; ks++) {
            uint32_t koff = (uint32_t)ks * 32;
            uint32_t a0[4], a1[4];
            ldsm_x4(a0, aAddr0 + koff);
            ldsm_x4(a1, aAddr1 + koff);
            uint32_t b[4][2];
            #pragma unroll
            for (int nt = 0; nt < 4; nt++)
                ldsm_x2(b[nt], bAddr + (uint32_t)nt * 8 * NGS * 2 + koff);
            #pragma unroll
            for (int nt = 0; nt < 4; nt++) {
                mma_f16(acc[0][nt], a0, b[nt]);
                mma_f16(acc[1][nt], a1, b[nt]);
            }
        }
    }
    __syncthreads();

    {
        int g = lane >> 2, t2 = (lane & 3) * 2;
        #pragma unroll
        for (int mt = 0; mt < 2; mt++)
            #pragma unroll
            for (int nt = 0; nt < 4; nt++) {
                int r0 = wm + mt * 16 + g, c0 = wn + nt * 8 + t2;
                float2 v0 = make_float2(acc[mt][nt][0], acc[mt][nt][1]);
                float2 v1 = make_float2(acc[mt][nt][2], acc[mt][nt][3]);
                if (RELU) {
                    v0.x = fmaxf(v0.x, 0.f); v0.y = fmaxf(v0.y, 0.f);
                    v1.x = fmaxf(v1.x, 0.f); v1.y = fmaxf(v1.y, 0.f);
                }
                *(float2*)(sD + r0 * SD_STRIDE + c0)       = v0;
                *(float2*)(sD + (r0 + 8) * SD_STRIDE + c0) = v1;
            }
    }
    __syncthreads();
    {
        int row = tid & 127, q = tid >> 7;
        if (m0 + row < NN) {
            const float4* sp = (const float4*)(sD + row * SD_STRIDE + q * 32);
            float* orow = out + (size_t)(m0 + row) * H + q * 32;
            #pragma unroll
            for (int i = 0; i < 8; i++) *(float4*)(orow + i * 4) = sp[i];
        }
    }
}

// ---- initial edge layer: h0 = relu(P[src] + bond @ WbT) (fp16) -------------
__global__ __launch_bounds__(256) void init_edges(const float* __restrict__ bond,
                                                  const void* __restrict__ src) {
    __shared__ float sWb[BF * H];
    for (int i = threadIdx.x; i < BF * H; i += 256) sWb[i] = g_WbT[i];
    __syncthreads();
    int warp = threadIdx.x >> 5, lane = threadIdx.x & 31;
    for (long e0 = (long)blockIdx.x * 8; e0 < NE; e0 += (long)gridDim.x * 8) {
        long e = e0 + warp;
        int s = ld_idx(src, e);
        int q = lane * 4;
        float4 acc = *(const float4*)(g_P + (size_t)s * H + q);
        const float* br = bond + e * BF;
        #pragma unroll
        for (int k = 0; k < BF; k++) {
            float b = __ldg(br + k);
            float4 w = *(const float4*)(sWb + k * H + q);
            acc.x += b * w.x; acc.y += b * w.y; acc.z += b * w.z; acc.w += b * w.w;
        }
        acc.x = fmaxf(acc.x, 0.f); acc.y = fmaxf(acc.y, 0.f);
        acc.z = fmaxf(acc.z, 0.f); acc.w = fmaxf(acc.w, 0.f);
        __half2 p0 = __floats2half2_rn(acc.x, acc.y);
        __half2 p1 = __floats2half2_rn(acc.z, acc.w);
        *(uint2*)(g_h + (size_t)e * H + q) = make_uint2(*(uint32_t*)&p0, *(uint32_t*)&p1);
    }
}

// ---------------- edge GEMM: 3-stage A pipeline, B frags in registers --------
// smem: B | A stage0 | A stage1 | A stage2 | D staging (dedicated).
// Two cp.async groups (tiles t+1, t+2) kept in flight at all times.
__global__ __launch_bounds__(512, 1) void egemm0(
    const __half* __restrict__ Ag,
    const uint4* __restrict__ B4,
    __half* __restrict__ Yout, float* __restrict__ Sout,
    const void* __restrict__ dstp)
{
    extern __shared__ __align__(16) char dyn[];
    __half* sB = (__half*)dyn;
    __half* st[3];
    st[0] = sB + BMAT;
    st[1] = st[0] + BMAT;
    st[2] = st[1] + BMAT;
    float* sD = (float*)(st[2] + BMAT);   // dedicated fp32 staging

    int tid = threadIdx.x, lane = tid & 31, wid = tid >> 5;
    long tile0 = (long)blockIdx.x * TILES_PER_CTA;

    // prefetch tiles 0 and 1 (two groups in flight before anything else)
    #pragma unroll
    for (int p = 0; p < 2; p++) {
        uint32_t sp = smem_u32(st[p]);
        long e0 = (tile0 + p) * ETILE;
        #pragma unroll
        for (int it = 0; it < 4; it++) {
            int i = tid + it * 512;
            int r = i >> 4, c = i & 15;
            cp_async16(sp + (uint32_t)(r * SA_STRIDE + c * 8) * 2,
                       Ag + (size_t)(e0 + r) * H + c * 8);
        }
        cp_commit();
    }

    // B resident in smem
    #pragma unroll
    for (int it = 0; it < 4; it++) {
        int i = tid + it * 512;
        int r = i >> 4, c = i & 15;
        *(uint4*)(sB + r * SA_STRIDE + c * 8) = __ldg(B4 + i);
    }
    __syncthreads();

    int wm = (wid >> 2) * 32;
    int wn = (wid & 3) * 32;

    // hoist B fragments into registers (once per CTA)
    uint32_t bfr[8][4][2];
    {
        uint32_t bB = smem_u32(sB) + ((uint32_t)(wn + (lane & 7)) * SA_STRIDE + ((lane >> 3) & 1) * 8) * 2;
        const uint32_t nstep = 8 * SA_STRIDE * 2;
        #pragma unroll
        for (int ks = 0; ks < 8; ks++)
            #pragma unroll
            for (int nt = 0; nt < 4; nt++)
                ldsm_x2(bfr[ks][nt], bB + (uint32_t)nt * nstep + (uint32_t)ks * 32);
    }

    for (int t = 0; t < TILES_PER_CTA; t++) {
        long e0 = (tile0 + t) * ETILE;
        __half* sA = st[t % 3];

        // issue prefetch(t+2) into stage (t+2)%3 (retired 2 tiles ago), then
        // drain tile t's group (leave 2 groups pending).
        if (t + 2 < TILES_PER_CTA) {
            uint32_t sp = smem_u32(st[(t + 2) % 3]);
            long en = (tile0 + t + 2) * ETILE;
            #pragma unroll
            for (int it = 0; it < 4; it++) {
                int i = tid + it * 512;
                int r = i >> 4, c = i & 15;
                cp_async16(sp + (uint32_t)(r * SA_STRIDE + c * 8) * 2,
                           Ag + (size_t)(en + r) * H + c * 8);
            }
            cp_commit();
            cp_wait<2>();
        } else if (t + 1 < TILES_PER_CTA) {
            cp_wait<1>();
        } else {
            cp_wait<0>();
        }
        __syncthreads();

        float acc[2][4][4];
        #pragma unroll
        for (int mt = 0; mt < 2; mt++)
            #pragma unroll
            for (int nt = 0; nt < 4; nt++)
                #pragma unroll
                for (int i = 0; i < 4; i++) acc[mt][nt][i] = 0.f;

        {
            uint32_t aA = smem_u32(sA) + ((uint32_t)(wm + (lane & 15)) * SA_STRIDE + (lane >> 4) * 8) * 2;
            const uint32_t rstep = 16 * SA_STRIDE * 2;
            #pragma unroll
            for (int ks = 0; ks < 8; ks++) {
                uint32_t koff = (uint32_t)ks * 32;
                uint32_t a0[4], a1[4];
                ldsm_x4(a0, aA + koff);
                ldsm_x4(a1, aA + rstep + koff);
                #pragma unroll
                for (int nt = 0; nt < 4; nt++) {
                    mma_f16(acc[0][nt], a0, bfr[ks][nt]);
                    mma_f16(acc[1][nt], a1, bfr[ks][nt]);
                }
            }
        }
        __syncthreads();

        // D staging in dedicated region
        {
            int g = lane >> 2, t2 = (lane & 3) * 2;
            #pragma unroll
            for (int mt = 0; mt < 2; mt++)
                #pragma unroll
                for (int nt = 0; nt < 4; nt++) {
                    int r0 = wm + mt * 16 + g, c0 = wn + nt * 8 + t2;
                    *(float2*)(sD + r0 * SD_STRIDE + c0)       = make_float2(acc[mt][nt][0], acc[mt][nt][1]);
                    *(float2*)(sD + (r0 + 8) * SD_STRIDE + c0) = make_float2(acc[mt][nt][2], acc[mt][nt][3]);
                }
        }
        __syncthreads();

        // epilogue: Y (fp16) write + fp32 red scatter
        {
            int row = tid & 127, q = tid >> 7;
            long e = e0 + row;
            int d = ld_idx(dstp, e);
            const float4* sp = (const float4*)(sD + row * SD_STRIDE + q * 32);
            __half* yrow = Yout + (size_t)e * H + q * 32;
            float* srow = Sout + (size_t)d * H + q * 32;
            #pragma unroll
            for (int i = 0; i < 8; i++) {
                float4 v = sp[i];
                __half2 ha = __floats2half2_rn(v.x, v.y);
                __half2 hb = __floats2half2_rn(v.z, v.w);
                *(uint2*)(yrow + i * 4) = make_uint2(*(uint32_t*)&ha, *(uint32_t*)&hb);
                red4(srow + i * 4, v);
            }
        }
        __syncthreads();
    }
}

// ------- combine1: h = relu(S[src] - Y[rev]) -> g_h (fp16, streaming) --------
__global__ __launch_bounds__(256) void combine1(const float* __restrict__ S,
                                                const __half* __restrict__ Yv,
                                                const void* __restrict__ src,
                                                const void* __restrict__ rev) {
    long g = (long)blockIdx.x * 256 + threadIdx.x;
    long e = g >> 5;
    if (e >= NE) return;
    int q = (int)(g & 31) * 4;
    int s = ld_idx(src, e);
    long r = ld_idx(rev, e);
    float4 sv = *(const float4*)(S + (size_t)s * H + q);
    float4 yv = ld_y4(Yv + (size_t)r * H + q);
    float4 h;
    h.x = fmaxf(sv.x - yv.x, 0.f);
    h.y = fmaxf(sv.y - yv.y, 0.f);
    h.z = fmaxf(sv.z - yv.z, 0.f);
    h.w = fmaxf(sv.w - yv.w, 0.f);
    __half2 p0 = __floats2half2_rn(h.x, h.y);
    __half2 p1 = __floats2half2_rn(h.z, h.w);
    *(uint2*)(g_h + (size_t)e * H + q) = make_uint2(*(uint32_t*)&p0, *(uint32_t*)&p1);
}

// ------- combine2: scatter relu(S[src] - Y[rev]) into S3[dst] ----------------
__global__ __launch_bounds__(256) void combine2(const float* __restrict__ S,
                                                const __half* __restrict__ Yv,
                                                const void* __restrict__ src,
                                                const void* __restrict__ rev,
                                                float* __restrict__ S3,
                                                const void* __restrict__ dst) {
    long g = (long)blockIdx.x * 256 + threadIdx.x;
    long e = g >> 5;
    if (e >= NE) return;
    int q = (int)(g & 31) * 4;
    int s = ld_idx(src, e);
    long r = ld_idx(rev, e);
    int d = ld_idx(dst, e);
    float4 sv = *(const float4*)(S + (size_t)s * H + q);
    float4 yv = ld_y4(Yv + (size_t)r * H + q);
    float4 h;
    h.x = fmaxf(sv.x - yv.x, 0.f);
    h.y = fmaxf(sv.y - yv.y, 0.f);
    h.z = fmaxf(sv.z - yv.z, 0.f);
    h.w = fmaxf(sv.w - yv.w, 0.f);
    red4(S3 + (size_t)d * H + q, h);
}

// ---------------- launcher ----------------
extern "C" void kernel_launch(void* const* d_in, const int* in_sizes, int n_in,
                              void* d_out, int out_size) {
    const float* atom = (const float*)d_in[0];
    const float* bond = (const float*)d_in[1];
    const float* Wi   = (const float*)d_in[2];
    const float* Wh   = (const float*)d_in[3];
    const float* Wo   = (const float*)d_in[4];
    const void*  src  = d_in[5];
    const void*  dst  = d_in[6];
    const void*  rev  = d_in[7];
    float* out = (float*)d_out;

    __half *h, *y1, *y2, *B, *W1, *W2, *A1, *A2;
    float *P, *S1, *S2, *S3;
    cudaGetSymbolAddress((void**)&h,  g_h);
    cudaGetSymbolAddress((void**)&B,  g_B);
    cudaGetSymbolAddress((void**)&W1, g_W1);
    cudaGetSymbolAddress((void**)&W2, g_W2);
    cudaGetSymbolAddress((void**)&A1, g_A1);
    cudaGetSymbolAddress((void**)&A2, g_A2);
    cudaGetSymbolAddress((void**)&y1, g_y1);
    cudaGetSymbolAddress((void**)&y2, g_y2);
    cudaGetSymbolAddress((void**)&P,  g_P);
    cudaGetSymbolAddress((void**)&S1, g_S1);
    cudaGetSymbolAddress((void**)&S2, g_S2);
    cudaGetSymbolAddress((void**)&S3, g_S3);

    const int smemN  = 2 * NGMAT * 2 + 128 * SD_STRIDE * 4;   // 145408 B
    const int smemE0 = 4 * BMAT * 2 + 128 * SD_STRIDE * 4;    // 139264 + 67584 = 206848 B
    cudaFuncSetAttribute(ngemm<144, false>, cudaFuncAttributeMaxDynamicSharedMemorySize, smemN);
    cudaFuncSetAttribute(ngemm<288, true>,  cudaFuncAttributeMaxDynamicSharedMemorySize, smemN);
    cudaFuncSetAttribute(egemm0, cudaFuncAttributeMaxDynamicSharedMemorySize, smemE0);

    // 1: prep (zeros + weights + atom panel + idx detect)
    prep_all<<<ZB + WB + CB + 1, 256>>>(Wi, Wh, Wo, atom, (const unsigned int*)src,
                                        (float4*)S1, (float4*)S2, (float4*)S3);
    // 2: P = atom @ Wa^T  (fp16 single-pass)
    ngemm<144, false><<<NGRID, 512, smemN>>>(A1, W1, P);
    // 3: h0 = relu(P[src] + bond @ WbT)  (fp16)
    init_edges<<<2048, 256>>>(bond, src);
    // 4: iter 1: Y1 = h0 @ Wh^T (3-stage pipeline), scatter S1   (ncu capture slot)
    egemm0<<<EGRID, 512, smemE0>>>(h, (const uint4*)B, y1, S1, dst);
    // 5: h1 = relu(S1[src] - Y1[rev])  (fp16)
    combine1<<<NE * 32 / 256, 256>>>(S1, y1, src, rev);
    // 6: iter 2: Y2 = h1 @ Wh^T, scatter S2
    egemm0<<<EGRID, 512, smemE0>>>(h, (const uint4*)B, y2, S2, dst);
    // 7: scatter relu(S2[src] - Y2[rev]) into S3
    combine2<<<NE * 32 / 256, 256>>>(S2, y2, src, rev, S3, dst);
    // 8: [atom|S3] panel (fp16)
    cvt2<<<(int)(((long)NROWS_PAD * 288 + 511) / 512), 512>>>(atom, S3);
    // 9: out = relu([atom|S3] @ Wo^T)  (fp16 single-pass)
    ngemm<288, true><<<NGRID, 512, smemN>>>(A2, W2, out);
}

// round 16
// speedup vs baseline: 1.0973x; 1.0973x over previous
#include <cuda_runtime.h>
#include <cuda_fp16.h>
#include <cstdint>

#define NN 50000
#define NE 800000
#define AF 133
#define BF 14
#define H  128
#define SA_STRIDE 136
#define SD_STRIDE 132
#define BMAT (128 * SA_STRIDE)          // elems per 128x128 16-bit smem matrix
#define AMAT (64 * SA_STRIDE)           // elems per 64x128 A stage
#define ETILE 64
#define TILES_PER_CTA 5
#define EGRID (NE / ETILE / TILES_PER_CTA)   // 2500

#define NGS  152
#define NGMAT (128 * NGS)
#define NROWS_PAD 50048
#define NGRID 391

// ---------------- scratch ----------------
__device__ __half g_h [(size_t)NE * H];            // edge hidden (fp16)
__device__ __half g_y1[(size_t)NE * H];            // Y (fp16)
__device__ __half g_y2[(size_t)NE * H];
__device__ float g_P [(size_t)NN * H];
__device__ float g_S1[(size_t)NN * H];
__device__ float g_S2[(size_t)NN * H];
__device__ float g_S3[(size_t)NN * H];
__device__ float g_WbT[BF * H];
__device__ __half g_B [H * H];                     // Wh (fp16)  [n][k]
__device__ __half g_W1[128 * 144];                 // Wa padded (fp16) [n][k]
__device__ __half g_W2[128 * 288];                 // Wo padded (fp16) [n][k]
__device__ __half g_A1[(size_t)NROWS_PAD * 144];   // atom panel (fp16)
__device__ __half g_A2[(size_t)NROWS_PAD * 288];   // [atom|S3] panel (fp16)
__device__ int   g_idx64;

// ---------------- helpers ----------------
__device__ __forceinline__ int ld_idx(const void* p, long i) {
    if (g_idx64) return (int)__ldg((const long long*)p + i);
    return __ldg((const int*)p + i);
}
__device__ __forceinline__ void red4(float* p, float4 v) {
    asm volatile("red.global.add.v4.f32 [%0], {%1,%2,%3,%4};"
                 :: "l"(p), "f"(v.x), "f"(v.y), "f"(v.z), "f"(v.w) : "memory");
}
__device__ __forceinline__ uint32_t smem_u32(const void* p) {
    uint32_t a;
    asm("{ .reg .u64 t; cvta.to.shared.u64 t, %1; cvt.u32.u64 %0, t; }" : "=r"(a) : "l"(p));
    return a;
}
__device__ __forceinline__ void cp_async16(uint32_t sdst, const void* gsrc) {
    asm volatile("cp.async.cg.shared.global [%0], [%1], 16;" :: "r"(sdst), "l"(gsrc) : "memory");
}
__device__ __forceinline__ void cp_commit() {
    asm volatile("cp.async.commit_group;" ::: "memory");
}
template<int N> __device__ __forceinline__ void cp_wait() {
    asm volatile("cp.async.wait_group %0;" :: "n"(N) : "memory");
}
__device__ __forceinline__ void ldsm_x4(uint32_t (&r)[4], uint32_t addr) {
    asm volatile("ldmatrix.sync.aligned.m8n8.x4.shared.b16 {%0,%1,%2,%3}, [%4];"
                 : "=r"(r[0]), "=r"(r[1]), "=r"(r[2]), "=r"(r[3]) : "r"(addr));
}
__device__ __forceinline__ void ldsm_x2(uint32_t (&r)[2], uint32_t addr) {
    asm volatile("ldmatrix.sync.aligned.m8n8.x2.shared.b16 {%0,%1}, [%2];"
                 : "=r"(r[0]), "=r"(r[1]) : "r"(addr));
}
__device__ __forceinline__ void mma_f16(float (&d)[4], const uint32_t (&a)[4], const uint32_t (&b)[2]) {
    asm volatile("mma.sync.aligned.m16n8k16.row.col.f32.f16.f16.f32 "
                 "{%0,%1,%2,%3}, {%4,%5,%6,%7}, {%8,%9}, {%0,%1,%2,%3};"
                 : "+f"(d[0]), "+f"(d[1]), "+f"(d[2]), "+f"(d[3])
                 : "r"(a[0]), "r"(a[1]), "r"(a[2]), "r"(a[3]), "r"(b[0]), "r"(b[1]));
}
__device__ __forceinline__ float4 ld_y4(const __half* p) {
    uint2 raw = __ldg((const uint2*)p);
    __half2 h01 = *(__half2*)&raw.x;
    __half2 h23 = *(__half2*)&raw.y;
    float2 f01 = __half22float2(h01);
    float2 f23 = __half22float2(h23);
    return make_float4(f01.x, f01.y, f23.x, f23.y);
}

// ======= prep_all: zero S bufs | weight prep | atom panel | idx detect ======
#define ZB 18750
#define WB 144
#define CB 28152
__global__ __launch_bounds__(256) void prep_all(
    const float* __restrict__ Wi, const float* __restrict__ Wh,
    const float* __restrict__ Wo, const float* __restrict__ atom,
    const unsigned int* __restrict__ srcw,
    float4* __restrict__ S1, float4* __restrict__ S2, float4* __restrict__ S3)
{
    int b = blockIdx.x;
    if (b < ZB) {
        const long n = (long)NN * H / 4;
        long i = (long)b * 256 + threadIdx.x;
        float4 z = make_float4(0.f, 0.f, 0.f, 0.f);
        if (i < n) S1[i] = z;
        else if (i < 2 * n) S2[i - n] = z;
        else S3[i - 2 * n] = z;
        return;
    }
    b -= ZB;
    if (b < WB) {
        int i = b * 256 + threadIdx.x;
        if (i >= 128 * 288) return;
        if (i < BF * H) {
            int j = i & 127, k = i >> 7;
            g_WbT[i] = Wi[j * (AF + BF) + AF + k];
        }
        if (i < H * H)
            g_B[i] = __float2half_rn(Wh[i]);
        if (i < 128 * 144) {
            int n = i / 144, k = i % 144;
            g_W1[i] = __float2half_rn((k < AF) ? Wi[n * (AF + BF) + k] : 0.f);
        }
        {
            int n = i / 288, k = i % 288;
            g_W2[i] = __float2half_rn((k < AF + H) ? Wo[n * (AF + H) + k] : 0.f);
        }
        return;
    }
    b -= WB;
    if (b < CB) {
        long i = (long)b * 256 + threadIdx.x;
        int r = (int)(i / 144), c = (int)(i % 144);
        float v = (r < NN && c < AF) ? __ldg(atom + (size_t)r * AF + c) : 0.f;
        g_A1[i] = __float2half_rn(v);
        return;
    }
    __shared__ unsigned int s;
    if (threadIdx.x == 0) s = 0;
    __syncthreads();
    unsigned int v = srcw[threadIdx.x * 2 + 1] | srcw[2048 + threadIdx.x * 2 + 1];
    atomicOr(&s, v);
    __syncthreads();
    if (threadIdx.x == 0) g_idx64 = (s == 0u) ? 1 : 0;
}

// ---------------- cvt2: [atom|S3] panel (fp16) ----------------
__global__ void cvt2(const float* __restrict__ atom, const float* __restrict__ S3) {
    long i = (long)blockIdx.x * blockDim.x + threadIdx.x;
    if (i >= (long)NROWS_PAD * 288) return;
    int r = (int)(i / 288), c = (int)(i % 288);
    float v = 0.f;
    if (r < NN) {
        if (c < AF) v = __ldg(atom + (size_t)r * AF + c);
        else if (c < AF + H) v = __ldg(S3 + (size_t)r * H + (c - AF));
    }
    g_A2[i] = __float2half_rn(v);
}

// ---------------- node GEMM via mma.sync (single fp16, 1 pass) ---------------
template<int KPAD, bool RELU>
__global__ __launch_bounds__(512, 1) void ngemm(
    const __half* __restrict__ Ag, const __half* __restrict__ Wg,
    float* __restrict__ out)
{
    extern __shared__ __align__(16) char dyn[];
    __half* sB = (__half*)dyn;
    __half* sA = sB + NGMAT;
    float*  sD = (float*)(sA + NGMAT);   // dedicated staging

    int tid = threadIdx.x, lane = tid & 31, wid = tid >> 5;
    int m0 = blockIdx.x * 128;
    int wm = (wid >> 2) * 32, wn = (wid & 3) * 32;

    float acc[2][4][4];
    #pragma unroll
    for (int mt = 0; mt < 2; mt++)
        #pragma unroll
        for (int nt = 0; nt < 4; nt++)
            #pragma unroll
            for (int i = 0; i < 4; i++) acc[mt][nt][i] = 0.f;

    const int NCH = KPAD / 144;
    #pragma unroll
    for (int ch = 0; ch < NCH; ch++) {
        if (ch) __syncthreads();
        for (int i = tid; i < 128 * 18; i += 512) {
            int r = i / 18, c = i % 18;
            int go = r * KPAD + ch * 144 + c * 8;
            *(uint4*)(sB + r * NGS + c * 8) = *(const uint4*)(Wg + go);
        }
        for (int i = tid; i < 128 * 18; i += 512) {
            int r = i / 18, c = i % 18;
            size_t go = (size_t)(m0 + r) * KPAD + ch * 144 + c * 8;
            *(uint4*)(sA + r * NGS + c * 8) = *(const uint4*)(Ag + go);
        }
        __syncthreads();

        uint32_t aAddr0 = smem_u32(sA) + ((uint32_t)(wm + (lane & 15)) * NGS + (lane >> 4) * 8) * 2;
        uint32_t aAddr1 = aAddr0 + 16 * NGS * 2;
        uint32_t bAddr  = smem_u32(sB) + ((uint32_t)(wn + (lane & 7)) * NGS + ((lane >> 3) & 1) * 8) * 2;
        #pragma unroll
        for (int ks = 0; ks < 9; ks++) {
            uint32_t koff = (uint32_t)ks * 32;
            uint32_t a0[4], a1[4];
            ldsm_x4(a0, aAddr0 + koff);
            ldsm_x4(a1, aAddr1 + koff);
            uint32_t b[4][2];
            #pragma unroll
            for (int nt = 0; nt < 4; nt++)
                ldsm_x2(b[nt], bAddr + (uint32_t)nt * 8 * NGS * 2 + koff);
            #pragma unroll
            for (int nt = 0; nt < 4; nt++) {
                mma_f16(acc[0][nt], a0, b[nt]);
                mma_f16(acc[1][nt], a1, b[nt]);
            }
        }
    }
    __syncthreads();

    {
        int g = lane >> 2, t2 = (lane & 3) * 2;
        #pragma unroll
        for (int mt = 0; mt < 2; mt++)
            #pragma unroll
            for (int nt = 0; nt < 4; nt++) {
                int r0 = wm + mt * 16 + g, c0 = wn + nt * 8 + t2;
                float2 v0 = make_float2(acc[mt][nt][0], acc[mt][nt][1]);
                float2 v1 = make_float2(acc[mt][nt][2], acc[mt][nt][3]);
                if (RELU) {
                    v0.x = fmaxf(v0.x, 0.f); v0.y = fmaxf(v0.y, 0.f);
                    v1.x = fmaxf(v1.x, 0.f); v1.y = fmaxf(v1.y, 0.f);
                }
                *(float2*)(sD + r0 * SD_STRIDE + c0)       = v0;
                *(float2*)(sD + (r0 + 8) * SD_STRIDE + c0) = v1;
            }
    }
    __syncthreads();
    {
        int row = tid & 127, q = tid >> 7;
        if (m0 + row < NN) {
            const float4* sp = (const float4*)(sD + row * SD_STRIDE + q * 32);
            float* orow = out + (size_t)(m0 + row) * H + q * 32;
            #pragma unroll
            for (int i = 0; i < 8; i++) *(float4*)(orow + i * 4) = sp[i];
        }
    }
}

// ---- initial edge layer: h0 = relu(P[src] + bond @ WbT) (fp16) -------------
__global__ __launch_bounds__(256) void init_edges(const float* __restrict__ bond,
                                                  const void* __restrict__ src) {
    __shared__ float sWb[BF * H];
    for (int i = threadIdx.x; i < BF * H; i += 256) sWb[i] = g_WbT[i];
    __syncthreads();
    int warp = threadIdx.x >> 5, lane = threadIdx.x & 31;
    for (long e0 = (long)blockIdx.x * 8; e0 < NE; e0 += (long)gridDim.x * 8) {
        long e = e0 + warp;
        int s = ld_idx(src, e);
        int q = lane * 4;
        float4 acc = *(const float4*)(g_P + (size_t)s * H + q);
        const float* br = bond + e * BF;
        #pragma unroll
        for (int k = 0; k < BF; k++) {
            float b = __ldg(br + k);
            float4 w = *(const float4*)(sWb + k * H + q);
            acc.x += b * w.x; acc.y += b * w.y; acc.z += b * w.z; acc.w += b * w.w;
        }
        acc.x = fmaxf(acc.x, 0.f); acc.y = fmaxf(acc.y, 0.f);
        acc.z = fmaxf(acc.z, 0.f); acc.w = fmaxf(acc.w, 0.f);
        __half2 p0 = __floats2half2_rn(acc.x, acc.y);
        __half2 p1 = __floats2half2_rn(acc.z, acc.w);
        *(uint2*)(g_h + (size_t)e * H + q) = make_uint2(*(uint32_t*)&p0, *(uint32_t*)&p1);
    }
}

// ---------------- edge GEMM: 64-row tiles, 256 thr, 2 CTAs/SM ----------------
// smem per CTA: B(34KB) | A stage0(17KB) | A stage1(17KB) | sD(33KB) = 101.5KB.
// 2-stage cp.async double-buffer (R14-proven order), B fragments in registers.
__global__ __launch_bounds__(256, 2) void egemm0(
    const __half* __restrict__ Ag,
    const uint4* __restrict__ B4,
    __half* __restrict__ Yout, float* __restrict__ Sout,
    const void* __restrict__ dstp)
{
    extern __shared__ __align__(16) char dyn[];
    __half* sB = (__half*)dyn;
    __half* sSt0 = sB + BMAT;
    __half* sSt1 = sSt0 + AMAT;
    float* sD = (float*)(sSt1 + AMAT);   // dedicated fp32 staging (64 rows)

    int tid = threadIdx.x, lane = tid & 31, wid = tid >> 5;
    long tile0 = (long)blockIdx.x * TILES_PER_CTA;

    // prefetch tile 0 (64 rows x 16 chunks = 1024 over 256 threads)
    {
        uint32_t st = smem_u32(sSt0);
        long e0 = tile0 * ETILE;
        #pragma unroll
        for (int it = 0; it < 4; it++) {
            int i = tid + it * 256;
            int r = i >> 4, c = i & 15;
            cp_async16(st + (uint32_t)(r * SA_STRIDE + c * 8) * 2,
                       Ag + (size_t)(e0 + r) * H + c * 8);
        }
        cp_commit();
    }

    // B resident in smem (2048 chunks over 256 threads)
    #pragma unroll
    for (int it = 0; it < 8; it++) {
        int i = tid + it * 256;
        int r = i >> 4, c = i & 15;
        *(uint4*)(sB + r * SA_STRIDE + c * 8) = __ldg(B4 + i);
    }
    __syncthreads();

    int wm = (wid >> 2) * 32;          // {0, 32}
    int wn = (wid & 3) * 32;

    // hoist B fragments into registers (once per CTA)
    uint32_t bfr[8][4][2];
    {
        uint32_t bB = smem_u32(sB) + ((uint32_t)(wn + (lane & 7)) * SA_STRIDE + ((lane >> 3) & 1) * 8) * 2;
        const uint32_t nstep = 8 * SA_STRIDE * 2;
        #pragma unroll
        for (int ks = 0; ks < 8; ks++)
            #pragma unroll
            for (int nt = 0; nt < 4; nt++)
                ldsm_x2(bfr[ks][nt], bB + (uint32_t)nt * nstep + (uint32_t)ks * 32);
    }

    for (int t = 0; t < TILES_PER_CTA; t++) {
        long e0 = (tile0 + t) * ETILE;
        __half* sA = (t & 1) ? sSt1 : sSt0;

        // issue prefetch(t+1) FIRST, then drain tile t
        if (t + 1 < TILES_PER_CTA) {
            __half* nx = (t & 1) ? sSt0 : sSt1;
            uint32_t st = smem_u32(nx);
            long en = (tile0 + t + 1) * ETILE;
            #pragma unroll
            for (int it = 0; it < 4; it++) {
                int i = tid + it * 256;
                int r = i >> 4, c = i & 15;
                cp_async16(st + (uint32_t)(r * SA_STRIDE + c * 8) * 2,
                           Ag + (size_t)(en + r) * H + c * 8);
            }
            cp_commit();
            cp_wait<1>();
        } else {
            cp_wait<0>();
        }
        __syncthreads();

        float acc[2][4][4];
        #pragma unroll
        for (int mt = 0; mt < 2; mt++)
            #pragma unroll
            for (int nt = 0; nt < 4; nt++)
                #pragma unroll
                for (int i = 0; i < 4; i++) acc[mt][nt][i] = 0.f;

        {
            uint32_t aA = smem_u32(sA) + ((uint32_t)(wm + (lane & 15)) * SA_STRIDE + (lane >> 4) * 8) * 2;
            const uint32_t rstep = 16 * SA_STRIDE * 2;
            #pragma unroll
            for (int ks = 0; ks < 8; ks++) {
                uint32_t koff = (uint32_t)ks * 32;
                uint32_t a0[4], a1[4];
                ldsm_x4(a0, aA + koff);
                ldsm_x4(a1, aA + rstep + koff);
                #pragma unroll
                for (int nt = 0; nt < 4; nt++) {
                    mma_f16(acc[0][nt], a0, bfr[ks][nt]);
                    mma_f16(acc[1][nt], a1, bfr[ks][nt]);
                }
            }
        }
        __syncthreads();

        // D staging in dedicated region (64 rows)
        {
            int g = lane >> 2, t2 = (lane & 3) * 2;
            #pragma unroll
            for (int mt = 0; mt < 2; mt++)
                #pragma unroll
                for (int nt = 0; nt < 4; nt++) {
                    int r0 = wm + mt * 16 + g, c0 = wn + nt * 8 + t2;
                    *(float2*)(sD + r0 * SD_STRIDE + c0)       = make_float2(acc[mt][nt][0], acc[mt][nt][1]);
                    *(float2*)(sD + (r0 + 8) * SD_STRIDE + c0) = make_float2(acc[mt][nt][2], acc[mt][nt][3]);
                }
        }
        __syncthreads();

        // epilogue: thread: row tid&63, 32-col chunk tid>>6
        {
            int row = tid & 63, q = tid >> 6;
            long e = e0 + row;
            int d = ld_idx(dstp, e);
            const float4* sp = (const float4*)(sD + row * SD_STRIDE + q * 32);
            __half* yrow = Yout + (size_t)e * H + q * 32;
            float* srow = Sout + (size_t)d * H + q * 32;
            #pragma unroll
            for (int i = 0; i < 8; i++) {
                float4 v = sp[i];
                __half2 ha = __floats2half2_rn(v.x, v.y);
                __half2 hb = __floats2half2_rn(v.z, v.w);
                *(uint2*)(yrow + i * 4) = make_uint2(*(uint32_t*)&ha, *(uint32_t*)&hb);
                red4(srow + i * 4, v);
            }
        }
        __syncthreads();
    }
}

// ------- combine1: h = relu(S[src] - Y[rev]) -> g_h (fp16, streaming) --------
__global__ __launch_bounds__(256) void combine1(const float* __restrict__ S,
                                                const __half* __restrict__ Yv,
                                                const void* __restrict__ src,
                                                const void* __restrict__ rev) {
    long g = (long)blockIdx.x * 256 + threadIdx.x;
    long e = g >> 5;
    if (e >= NE) return;
    int q = (int)(g & 31) * 4;
    int s = ld_idx(src, e);
    long r = ld_idx(rev, e);
    float4 sv = *(const float4*)(S + (size_t)s * H + q);
    float4 yv = ld_y4(Yv + (size_t)r * H + q);
    float4 h;
    h.x = fmaxf(sv.x - yv.x, 0.f);
    h.y = fmaxf(sv.y - yv.y, 0.f);
    h.z = fmaxf(sv.z - yv.z, 0.f);
    h.w = fmaxf(sv.w - yv.w, 0.f);
    __half2 p0 = __floats2half2_rn(h.x, h.y);
    __half2 p1 = __floats2half2_rn(h.z, h.w);
    *(uint2*)(g_h + (size_t)e * H + q) = make_uint2(*(uint32_t*)&p0, *(uint32_t*)&p1);
}

// ------- combine2: scatter relu(S[src] - Y[rev]) into S3[dst] ----------------
__global__ __launch_bounds__(256) void combine2(const float* __restrict__ S,
                                                const __half* __restrict__ Yv,
                                                const void* __restrict__ src,
                                                const void* __restrict__ rev,
                                                float* __restrict__ S3,
                                                const void* __restrict__ dst) {
    long g = (long)blockIdx.x * 256 + threadIdx.x;
    long e = g >> 5;
    if (e >= NE) return;
    int q = (int)(g & 31) * 4;
    int s = ld_idx(src, e);
    long r = ld_idx(rev, e);
    int d = ld_idx(dst, e);
    float4 sv = *(const float4*)(S + (size_t)s * H + q);
    float4 yv = ld_y4(Yv + (size_t)r * H + q);
    float4 h;
    h.x = fmaxf(sv.x - yv.x, 0.f);
    h.y = fmaxf(sv.y - yv.y, 0.f);
    h.z = fmaxf(sv.z - yv.z, 0.f);
    h.w = fmaxf(sv.w - yv.w, 0.f);
    red4(S3 + (size_t)d * H + q, h);
}

// ---------------- launcher ----------------
extern "C" void kernel_launch(void* const* d_in, const int* in_sizes, int n_in,
                              void* d_out, int out_size) {
    const float* atom = (const float*)d_in[0];
    const float* bond = (const float*)d_in[1];
    const float* Wi   = (const float*)d_in[2];
    const float* Wh   = (const float*)d_in[3];
    const float* Wo   = (const float*)d_in[4];
    const void*  src  = d_in[5];
    const void*  dst  = d_in[6];
    const void*  rev  = d_in[7];
    float* out = (float*)d_out;

    __half *h, *y1, *y2, *B, *W1, *W2, *A1, *A2;
    float *P, *S1, *S2, *S3;
    cudaGetSymbolAddress((void**)&h,  g_h);
    cudaGetSymbolAddress((void**)&B,  g_B);
    cudaGetSymbolAddress((void**)&W1, g_W1);
    cudaGetSymbolAddress((void**)&W2, g_W2);
    cudaGetSymbolAddress((void**)&A1, g_A1);
    cudaGetSymbolAddress((void**)&A2, g_A2);
    cudaGetSymbolAddress((void**)&y1, g_y1);
    cudaGetSymbolAddress((void**)&y2, g_y2);
    cudaGetSymbolAddress((void**)&P,  g_P);
    cudaGetSymbolAddress((void**)&S1, g_S1);
    cudaGetSymbolAddress((void**)&S2, g_S2);
    cudaGetSymbolAddress((void**)&S3, g_S3);

    const int smemN  = 2 * NGMAT * 2 + 128 * SD_STRIDE * 4;            // 145408 B
    const int smemE0 = BMAT * 2 + 2 * AMAT * 2 + 64 * SD_STRIDE * 4;   // 34816+34816+33792 = 103424 B
    cudaFuncSetAttribute(ngemm<144, false>, cudaFuncAttributeMaxDynamicSharedMemorySize, smemN);
    cudaFuncSetAttribute(ngemm<288, true>,  cudaFuncAttributeMaxDynamicSharedMemorySize, smemN);
    cudaFuncSetAttribute(egemm0, cudaFuncAttributeMaxDynamicSharedMemorySize, smemE0);

    // 1: prep (zeros + weights + atom panel + idx detect)
    prep_all<<<ZB + WB + CB + 1, 256>>>(Wi, Wh, Wo, atom, (const unsigned int*)src,
                                        (float4*)S1, (float4*)S2, (float4*)S3);
    // 2: P = atom @ Wa^T  (fp16 single-pass)
    ngemm<144, false><<<NGRID, 512, smemN>>>(A1, W1, P);
    // 3: h0 = relu(P[src] + bond @ WbT)  (fp16)
    init_edges<<<2048, 256>>>(bond, src);
    // 4: iter 1: Y1 = h0 @ Wh^T (2 CTAs/SM), scatter S1   (ncu capture slot)
    egemm0<<<EGRID, 256, smemE0>>>(h, (const uint4*)B, y1, S1, dst);
    // 5: h1 = relu(S1[src] - Y1[rev])  (fp16)
    combine1<<<NE * 32 / 256, 256>>>(S1, y1, src, rev);
    // 6: iter 2: Y2 = h1 @ Wh^T, scatter S2
    egemm0<<<EGRID, 256, smemE0>>>(h, (const uint4*)B, y2, S2, dst);
    // 7: scatter relu(S2[src] - Y2[rev]) into S3
    combine2<<<NE * 32 / 256, 256>>>(S2, y2, src, rev, S3, dst);
    // 8: [atom|S3] panel (fp16)
    cvt2<<<(int)(((long)NROWS_PAD * 288 + 511) / 512), 512>>>(atom, S3);
    // 9: out = relu([atom|S3] @ Wo^T)  (fp16 single-pass)
    ngemm<288, true><<<NGRID, 512, smemN>>>(A2, W2, out);
}